// round 1
// baseline (speedup 1.0000x reference)
#include <cuda_runtime.h>

// Problem constants
#define Bn   4
#define Vn   6
#define Cn   256
#define HWn  1024
#define Sn   6144      // Vn * HWn
#define NHn  4
#define HDn  64
#define WIN  3

// Scratch (allocation-free rule: __device__ globals)
__device__ float g_q [(size_t)Bn * Sn  * Cn];   // 25.2 MB  [B,S,C]
__device__ float g_k [(size_t)Bn * HWn * Cn];   //  4.2 MB  [B,HW,C]
__device__ float g_v [(size_t)Bn * HWn * Cn];   //  4.2 MB
__device__ float g_ao[(size_t)Bn * Sn  * Cn];   // 25.2 MB  attention out [B,S,C]

// ---------------------------------------------------------------------------
// Q projection: q[b,s,:] = q_in[b,s,:] @ Wq + bq
// A[m][k] = x[((b*V+v)*C + k)*HW + hw],  m = (b*V+v)*1024 + hw
// M=24576, N=256, K=256. 64x64x16 tile, 16x16 threads, 4x4 per thread.
// ---------------------------------------------------------------------------
__global__ void qproj_kernel(const float* __restrict__ x,
                             const float* __restrict__ Wq,
                             const float* __restrict__ bq)
{
    __shared__ float As[16][64];
    __shared__ float Bs[16][64];
    const int tid = threadIdx.y * 16 + threadIdx.x;
    const int m0  = blockIdx.y * 64;
    const int n0  = blockIdx.x * 64;
    const int bv  = m0 >> 10;          // tile never crosses (b,v): 64 | 1024
    const int hw0 = m0 & 1023;
    const float* abase = x + (size_t)bv * Cn * HWn + hw0;
    const int lm = tid & 63;
    const int lk = tid >> 6;
    float acc[4][4] = {};

    for (int k0 = 0; k0 < 256; k0 += 16) {
        #pragma unroll
        for (int kk = lk; kk < 16; kk += 4) {
            As[kk][lm] = abase[(size_t)(k0 + kk) * HWn + lm];
            Bs[kk][lm] = Wq[(k0 + kk) * 256 + n0 + lm];
        }
        __syncthreads();
        #pragma unroll
        for (int kk = 0; kk < 16; kk++) {
            float4 av = *reinterpret_cast<const float4*>(&As[kk][threadIdx.y * 4]);
            float4 bw = *reinterpret_cast<const float4*>(&Bs[kk][threadIdx.x * 4]);
            float a[4] = {av.x, av.y, av.z, av.w};
            float b4[4] = {bw.x, bw.y, bw.z, bw.w};
            #pragma unroll
            for (int i = 0; i < 4; i++)
                #pragma unroll
                for (int j = 0; j < 4; j++)
                    acc[i][j] += a[i] * b4[j];
        }
        __syncthreads();
    }
    #pragma unroll
    for (int i = 0; i < 4; i++) {
        const int m = m0 + threadIdx.y * 4 + i;
        #pragma unroll
        for (int j = 0; j < 4; j++) {
            const int n = n0 + threadIdx.x * 4 + j;
            g_q[(size_t)m * 256 + n] = acc[i][j] + bq[n];
        }
    }
}

// ---------------------------------------------------------------------------
// K and V projection (fused, share A-tile): [4096 x 1536] @ [1536 x 256]
// A[m][k] = x[((b*V + k/256)*C + k%256)*HW + hw], m = b*1024 + hw
// ---------------------------------------------------------------------------
__global__ void kvproj_kernel(const float* __restrict__ x,
                              const float* __restrict__ Wk,
                              const float* __restrict__ bk,
                              const float* __restrict__ Wv,
                              const float* __restrict__ bvp)
{
    __shared__ float As [16][64];
    __shared__ float Bks[16][64];
    __shared__ float Bvs[16][64];
    const int tid = threadIdx.y * 16 + threadIdx.x;
    const int m0  = blockIdx.y * 64;
    const int n0  = blockIdx.x * 64;
    const int b   = m0 >> 10;
    const int hw0 = m0 & 1023;
    const int lm = tid & 63;
    const int lk = tid >> 6;
    float acck[4][4] = {};
    float accv[4][4] = {};

    for (int k0 = 0; k0 < 1536; k0 += 16) {
        const int vv = k0 >> 8;        // 16 | 256 => tile within one v
        const int c0 = k0 & 255;
        const float* abase = x + ((size_t)(b * Vn + vv) * Cn + c0) * HWn + hw0;
        #pragma unroll
        for (int kk = lk; kk < 16; kk += 4) {
            As [kk][lm] = abase[(size_t)kk * HWn + lm];
            Bks[kk][lm] = Wk[(k0 + kk) * 256 + n0 + lm];
            Bvs[kk][lm] = Wv[(k0 + kk) * 256 + n0 + lm];
        }
        __syncthreads();
        #pragma unroll
        for (int kk = 0; kk < 16; kk++) {
            float4 av = *reinterpret_cast<const float4*>(&As [kk][threadIdx.y * 4]);
            float4 kw = *reinterpret_cast<const float4*>(&Bks[kk][threadIdx.x * 4]);
            float4 vw = *reinterpret_cast<const float4*>(&Bvs[kk][threadIdx.x * 4]);
            float a[4]  = {av.x, av.y, av.z, av.w};
            float kb[4] = {kw.x, kw.y, kw.z, kw.w};
            float vb[4] = {vw.x, vw.y, vw.z, vw.w};
            #pragma unroll
            for (int i = 0; i < 4; i++)
                #pragma unroll
                for (int j = 0; j < 4; j++) {
                    acck[i][j] += a[i] * kb[j];
                    accv[i][j] += a[i] * vb[j];
                }
        }
        __syncthreads();
    }
    #pragma unroll
    for (int i = 0; i < 4; i++) {
        const int m = m0 + threadIdx.y * 4 + i;
        #pragma unroll
        for (int j = 0; j < 4; j++) {
            const int n = n0 + threadIdx.x * 4 + j;
            g_k[(size_t)m * 256 + n] = acck[i][j] + bk[n];
            g_v[(size_t)m * 256 + n] = accv[i][j] + bvp[n];
        }
    }
}

// ---------------------------------------------------------------------------
// Fused masked-softmax attention (flash-style online softmax).
// One thread = one query row. q (scaled) + accumulator live in registers;
// K/V streamed through SMEM in 16-key tiles (broadcast LDS.128 reads).
// Mask: logits[j] -= 1e9 for j in [s-3, s+3]  (exp underflows to 0 exactly).
// ---------------------------------------------------------------------------
__global__ void __launch_bounds__(128) attn_kernel()
{
    __shared__ float4 ks4[16 * 16];   // 16 keys x 64 floats
    __shared__ float4 vs4[16 * 16];
    const int b  = blockIdx.z;
    const int h  = blockIdx.y;
    const int sg = blockIdx.x * 128 + threadIdx.x;   // global query index

    const float4* qrow = reinterpret_cast<const float4*>(
        g_q + ((size_t)(b * Sn + sg)) * Cn + h * HDn);
    float qr[64];
    #pragma unroll
    for (int d4 = 0; d4 < 16; d4++) {
        float4 t = qrow[d4];
        qr[d4*4+0] = t.x * 0.125f;   // fold 1/sqrt(hd)
        qr[d4*4+1] = t.y * 0.125f;
        qr[d4*4+2] = t.z * 0.125f;
        qr[d4*4+3] = t.w * 0.125f;
    }
    float acc[64];
    #pragma unroll
    for (int d = 0; d < 64; d++) acc[d] = 0.f;
    float mrun = -1e30f, lrun = 0.f;

    const float4* kbase = reinterpret_cast<const float4*>(
        g_k + (size_t)b * HWn * Cn + h * HDn);
    const float4* vbase = reinterpret_cast<const float4*>(
        g_v + (size_t)b * HWn * Cn + h * HDn);
    // row stride: 256 floats = 64 float4

    for (int jt = 0; jt < HWn; jt += 16) {
        __syncthreads();
        for (int idx = threadIdx.x; idx < 256; idx += 128) {
            const int r = idx >> 4, d4 = idx & 15;
            ks4[idx] = kbase[(size_t)(jt + r) * 64 + d4];
            vs4[idx] = vbase[(size_t)(jt + r) * 64 + d4];
        }
        __syncthreads();

        float sj[16];
        #pragma unroll
        for (int j = 0; j < 16; j++) {
            float s = 0.f;
            const float4* kp = &ks4[j * 16];
            #pragma unroll
            for (int d4 = 0; d4 < 16; d4++) {
                float4 kk = kp[d4];
                s += qr[d4*4+0]*kk.x + qr[d4*4+1]*kk.y
                   + qr[d4*4+2]*kk.z + qr[d4*4+3]*kk.w;
            }
            const int jg = jt + j;
            if (jg >= sg - WIN && jg <= sg + WIN) s -= 1e9f;
            sj[j] = s;
        }
        float tm = sj[0];
        #pragma unroll
        for (int j = 1; j < 16; j++) tm = fmaxf(tm, sj[j]);
        const float mn   = fmaxf(mrun, tm);
        const float corr = __expf(mrun - mn);
        mrun = mn;
        lrun *= corr;
        #pragma unroll
        for (int d = 0; d < 64; d++) acc[d] *= corr;
        #pragma unroll
        for (int j = 0; j < 16; j++) {
            const float p = __expf(sj[j] - mn);
            lrun += p;
            const float4* vp = &vs4[j * 16];
            #pragma unroll
            for (int d4 = 0; d4 < 16; d4++) {
                float4 vv = vp[d4];
                acc[d4*4+0] += p * vv.x;
                acc[d4*4+1] += p * vv.y;
                acc[d4*4+2] += p * vv.z;
                acc[d4*4+3] += p * vv.w;
            }
        }
    }

    const float inv = 1.f / lrun;
    float4* orow = reinterpret_cast<float4*>(
        g_ao + ((size_t)(b * Sn + sg)) * Cn + h * HDn);
    #pragma unroll
    for (int d4 = 0; d4 < 16; d4++) {
        float4 t;
        t.x = acc[d4*4+0] * inv;
        t.y = acc[d4*4+1] * inv;
        t.z = acc[d4*4+2] * inv;
        t.w = acc[d4*4+3] * inv;
        orow[d4] = t;
    }
}

// ---------------------------------------------------------------------------
// Output projection + reshape-scatter + residual.
// Y[m][n] = ao[m,:] @ Wo[:,n] + bo[n];  m = (b*V+v)*1024 + hw
// out flat = ((b*V+v)*256 + (hw>>2))*1024 + (hw&3)*256 + n  (reshape mixing)
// residual: x.reshape is identity flat => out[flat] = Y + x[flat]
// ---------------------------------------------------------------------------
__global__ void oproj_kernel(const float* __restrict__ x,
                             const float* __restrict__ Wo,
                             const float* __restrict__ bo,
                             float* __restrict__ out)
{
    __shared__ float As[16][64];
    __shared__ float Bs[16][64];
    const int tid = threadIdx.y * 16 + threadIdx.x;
    const int m0  = blockIdx.y * 64;
    const int n0  = blockIdx.x * 64;
    const int lm = tid & 63;
    const int lk = tid >> 6;
    const int lrow = tid >> 2;          // 0..63
    const int lc4  = (tid & 3) * 4;     // 0,4,8,12
    float acc[4][4] = {};

    for (int k0 = 0; k0 < 256; k0 += 16) {
        // A is row-major [M, 256]: load float4 along k, scatter-transpose to SMEM
        float4 a4 = *reinterpret_cast<const float4*>(
            &g_ao[(size_t)(m0 + lrow) * 256 + k0 + lc4]);
        As[lc4 + 0][lrow] = a4.x;
        As[lc4 + 1][lrow] = a4.y;
        As[lc4 + 2][lrow] = a4.z;
        As[lc4 + 3][lrow] = a4.w;
        #pragma unroll
        for (int kk = lk; kk < 16; kk += 4)
            Bs[kk][lm] = Wo[(k0 + kk) * 256 + n0 + lm];
        __syncthreads();
        #pragma unroll
        for (int kk = 0; kk < 16; kk++) {
            float4 av = *reinterpret_cast<const float4*>(&As[kk][threadIdx.y * 4]);
            float4 bw = *reinterpret_cast<const float4*>(&Bs[kk][threadIdx.x * 4]);
            float a[4]  = {av.x, av.y, av.z, av.w};
            float b4[4] = {bw.x, bw.y, bw.z, bw.w};
            #pragma unroll
            for (int i = 0; i < 4; i++)
                #pragma unroll
                for (int j = 0; j < 4; j++)
                    acc[i][j] += a[i] * b4[j];
        }
        __syncthreads();
    }

    const int nbase = n0 + threadIdx.x * 4;
    const float4 br = *reinterpret_cast<const float4*>(&bo[nbase]);
    #pragma unroll
    for (int i = 0; i < 4; i++) {
        const int m  = m0 + threadIdx.y * 4 + i;
        const int bv = m >> 10;
        const int hw = m & 1023;
        const size_t flat = ((size_t)(bv * 256 + (hw >> 2))) * 1024
                          + (size_t)(hw & 3) * 256 + nbase;
        const float4 xr = *reinterpret_cast<const float4*>(&x[flat]);
        float4 o;
        o.x = acc[i][0] + br.x + xr.x;
        o.y = acc[i][1] + br.y + xr.y;
        o.z = acc[i][2] + br.z + xr.z;
        o.w = acc[i][3] + br.w + xr.w;
        *reinterpret_cast<float4*>(&out[flat]) = o;
    }
}

// ---------------------------------------------------------------------------
extern "C" void kernel_launch(void* const* d_in, const int* in_sizes, int n_in,
                              void* d_out, int out_size)
{
    const float* x  = (const float*)d_in[0];
    const float* Wq = (const float*)d_in[1];
    const float* bq = (const float*)d_in[2];
    const float* Wk = (const float*)d_in[3];
    const float* bk = (const float*)d_in[4];
    const float* Wv = (const float*)d_in[5];
    const float* bv = (const float*)d_in[6];
    const float* Wo = (const float*)d_in[7];
    const float* bo = (const float*)d_in[8];
    float* out = (float*)d_out;

    dim3 blk(16, 16);
    qproj_kernel <<<dim3(4, 384), blk>>>(x, Wq, bq);
    kvproj_kernel<<<dim3(4, 64),  blk>>>(x, Wk, bk, Wv, bv);
    attn_kernel  <<<dim3(48, 4, 4), 128>>>();
    oproj_kernel <<<dim3(4, 384), blk>>>(x, Wo, bo, out);
}

// round 2
// speedup vs baseline: 2.5893x; 2.5893x over previous
#include <cuda_runtime.h>
#include <cuda_fp16.h>
#include <cstdint>

// Problem constants
#define Bn   4
#define Vn   6
#define Cn   256
#define HWn  1024
#define Sn   6144      // Vn * HWn
#define NHn  4
#define HDn  64
#define WIN  3

// Scratch (allocation-free rule: __device__ globals)
__device__ float  g_q [(size_t)Bn * Sn  * Cn];          // 25.2 MB  [B,S,C]
__device__ float  g_k [(size_t)Bn * HWn * Cn];          //  4.2 MB  [B,HW,C]
__device__ __half g_vt[(size_t)Bn * Cn  * HWn];         //  2.1 MB  [B,C,HW]  (transposed, fp16)
__device__ float  g_ao[(size_t)Bn * Sn  * Cn];          // 25.2 MB  [B,S,C]

// ---------------------------------------------------------------------------
// mma.sync helpers (Ampere-layout HMMA, valid on sm_103a)
// ---------------------------------------------------------------------------
__device__ __forceinline__ void mma_tf32(float* d, const uint32_t* a,
                                         uint32_t b0, uint32_t b1)
{
    asm volatile(
        "mma.sync.aligned.m16n8k8.row.col.f32.tf32.tf32.f32 "
        "{%0,%1,%2,%3}, {%4,%5,%6,%7}, {%8,%9}, {%0,%1,%2,%3};"
        : "+f"(d[0]), "+f"(d[1]), "+f"(d[2]), "+f"(d[3])
        : "r"(a[0]), "r"(a[1]), "r"(a[2]), "r"(a[3]), "r"(b0), "r"(b1));
}

__device__ __forceinline__ void mma_f16(float* d, const uint32_t* a,
                                        uint32_t b0, uint32_t b1)
{
    asm volatile(
        "mma.sync.aligned.m16n8k16.row.col.f32.f16.f16.f32 "
        "{%0,%1,%2,%3}, {%4,%5,%6,%7}, {%8,%9}, {%0,%1,%2,%3};"
        : "+f"(d[0]), "+f"(d[1]), "+f"(d[2]), "+f"(d[3])
        : "r"(a[0]), "r"(a[1]), "r"(a[2]), "r"(a[3]), "r"(b0), "r"(b1));
}

__device__ __forceinline__ float tf32r(float x)
{
    uint32_t u;
    asm("cvt.rna.tf32.f32 %0, %1;" : "=r"(u) : "f"(x));
    return __uint_as_float(u);
}

__device__ __forceinline__ uint32_t pack_h2(float a, float b)
{
    __half2 h = __floats2half2_rn(a, b);   // low = a, high = b
    return *reinterpret_cast<uint32_t*>(&h);
}

// ---------------------------------------------------------------------------
// Q projection: q[b,s,:] = q_in[b,s,:] @ Wq + bq   (unchanged SIMT)
// ---------------------------------------------------------------------------
__global__ void qproj_kernel(const float* __restrict__ x,
                             const float* __restrict__ Wq,
                             const float* __restrict__ bq)
{
    __shared__ float As[16][64];
    __shared__ float Bs[16][64];
    const int tid = threadIdx.y * 16 + threadIdx.x;
    const int m0  = blockIdx.y * 64;
    const int n0  = blockIdx.x * 64;
    const int bv  = m0 >> 10;
    const int hw0 = m0 & 1023;
    const float* abase = x + (size_t)bv * Cn * HWn + hw0;
    const int lm = tid & 63;
    const int lk = tid >> 6;
    float acc[4][4] = {};

    for (int k0 = 0; k0 < 256; k0 += 16) {
        #pragma unroll
        for (int kk = lk; kk < 16; kk += 4) {
            As[kk][lm] = abase[(size_t)(k0 + kk) * HWn + lm];
            Bs[kk][lm] = Wq[(k0 + kk) * 256 + n0 + lm];
        }
        __syncthreads();
        #pragma unroll
        for (int kk = 0; kk < 16; kk++) {
            float4 av = *reinterpret_cast<const float4*>(&As[kk][threadIdx.y * 4]);
            float4 bw = *reinterpret_cast<const float4*>(&Bs[kk][threadIdx.x * 4]);
            float a[4] = {av.x, av.y, av.z, av.w};
            float b4[4] = {bw.x, bw.y, bw.z, bw.w};
            #pragma unroll
            for (int i = 0; i < 4; i++)
                #pragma unroll
                for (int j = 0; j < 4; j++)
                    acc[i][j] += a[i] * b4[j];
        }
        __syncthreads();
    }
    #pragma unroll
    for (int i = 0; i < 4; i++) {
        const int m = m0 + threadIdx.y * 4 + i;
        #pragma unroll
        for (int j = 0; j < 4; j++) {
            const int n = n0 + threadIdx.x * 4 + j;
            g_q[(size_t)m * 256 + n] = acc[i][j] + bq[n];
        }
    }
}

// ---------------------------------------------------------------------------
// K and V projection (fused). K -> fp32 [B,HW,C]; V -> fp16 TRANSPOSED [B,C,HW]
// ---------------------------------------------------------------------------
__global__ void kvproj_kernel(const float* __restrict__ x,
                              const float* __restrict__ Wk,
                              const float* __restrict__ bk,
                              const float* __restrict__ Wv,
                              const float* __restrict__ bvp)
{
    __shared__ float As [16][64];
    __shared__ float Bks[16][64];
    __shared__ float Bvs[16][64];
    const int tid = threadIdx.y * 16 + threadIdx.x;
    const int m0  = blockIdx.y * 64;
    const int n0  = blockIdx.x * 64;
    const int b   = m0 >> 10;
    const int hw0 = m0 & 1023;
    const int lm = tid & 63;
    const int lk = tid >> 6;
    float acck[4][4] = {};
    float accv[4][4] = {};

    for (int k0 = 0; k0 < 1536; k0 += 16) {
        const int vv = k0 >> 8;
        const int c0 = k0 & 255;
        const float* abase = x + ((size_t)(b * Vn + vv) * Cn + c0) * HWn + hw0;
        #pragma unroll
        for (int kk = lk; kk < 16; kk += 4) {
            As [kk][lm] = abase[(size_t)kk * HWn + lm];
            Bks[kk][lm] = Wk[(k0 + kk) * 256 + n0 + lm];
            Bvs[kk][lm] = Wv[(k0 + kk) * 256 + n0 + lm];
        }
        __syncthreads();
        #pragma unroll
        for (int kk = 0; kk < 16; kk++) {
            float4 av = *reinterpret_cast<const float4*>(&As [kk][threadIdx.y * 4]);
            float4 kw = *reinterpret_cast<const float4*>(&Bks[kk][threadIdx.x * 4]);
            float4 vw = *reinterpret_cast<const float4*>(&Bvs[kk][threadIdx.x * 4]);
            float a[4]  = {av.x, av.y, av.z, av.w};
            float kb[4] = {kw.x, kw.y, kw.z, kw.w};
            float vb[4] = {vw.x, vw.y, vw.z, vw.w};
            #pragma unroll
            for (int i = 0; i < 4; i++)
                #pragma unroll
                for (int j = 0; j < 4; j++) {
                    acck[i][j] += a[i] * kb[j];
                    accv[i][j] += a[i] * vb[j];
                }
        }
        __syncthreads();
    }
    #pragma unroll
    for (int i = 0; i < 4; i++) {
        const int m  = m0 + threadIdx.y * 4 + i;
        const int hw = m & 1023;
        #pragma unroll
        for (int j = 0; j < 4; j++) {
            const int n = n0 + threadIdx.x * 4 + j;
            g_k[(size_t)m * 256 + n] = acck[i][j] + bk[n];
            g_vt[(((size_t)(b * 256 + n)) << 10) + hw] =
                __float2half(accv[i][j] + bvp[n]);
        }
    }
}

// ---------------------------------------------------------------------------
// Flash attention with mma.sync: tf32 QK^T + fp16 PV, online softmax.
// CTA = 64 queries (4 warps x m16), iterate 16 key-tiles of 64.
// Q fragments resident in registers; K staged fp32(tf32-rounded) in SMEM;
// V staged fp16 [dim][key] (already transposed in gmem).
// ---------------------------------------------------------------------------
__global__ void __launch_bounds__(128) attn_kernel()
{
    __shared__ float  Ks[64 * 68];      // [key][dim], pad 68 (conflict-free)
    __shared__ __half Vt[64 * 72];      // [dim][key], pad 72 (conflict-free)

    const int b  = blockIdx.z;
    const int h  = blockIdx.y;
    const int s0 = blockIdx.x * 64;
    const int w    = threadIdx.x >> 5;
    const int lane = threadIdx.x & 31;
    const int g = lane >> 2;            // group (row within m16)
    const int t = lane & 3;             // thread-in-group (col quad)

    // --- Q fragments: rows s0+16w+{g,g+8}, dims h*64.. ; scale folded; tf32 ---
    const float* qbase = g_q + ((size_t)(b * Sn + s0 + w * 16)) * Cn + h * HDn;
    uint32_t Qfr[8][4];
    #pragma unroll
    for (int ks = 0; ks < 8; ks++) {
        Qfr[ks][0] = __float_as_uint(tf32r(qbase[(size_t) g      * 256 + ks * 8 + t    ] * 0.125f));
        Qfr[ks][1] = __float_as_uint(tf32r(qbase[(size_t)(g + 8) * 256 + ks * 8 + t    ] * 0.125f));
        Qfr[ks][2] = __float_as_uint(tf32r(qbase[(size_t) g      * 256 + ks * 8 + t + 4] * 0.125f));
        Qfr[ks][3] = __float_as_uint(tf32r(qbase[(size_t)(g + 8) * 256 + ks * 8 + t + 4] * 0.125f));
    }

    float O[8][4];
    #pragma unroll
    for (int i = 0; i < 8; i++) { O[i][0] = O[i][1] = O[i][2] = O[i][3] = 0.f; }
    float m0r = -1e30f, m1r = -1e30f, l0 = 0.f, l1 = 0.f;

    const float*  kg = g_k  + (size_t)b * HWn * Cn + h * HDn;       // row stride 256
    const __half* vg = g_vt + (((size_t)(b * 256 + h * 64)) << 10); // row stride 1024

    const int r0 = s0 + w * 16 + g;
    const int r1 = r0 + 8;

    for (int jt = 0; jt < HWn; jt += 64) {
        __syncthreads();
        // stage K tile (tf32-rounded fp32)
        #pragma unroll
        for (int i = 0; i < 8; i++) {
            const int f4  = i * 128 + threadIdx.x;      // 0..1023
            const int row = f4 >> 4, c4 = f4 & 15;
            float4 kv = *reinterpret_cast<const float4*>(
                kg + (size_t)(jt + row) * 256 + c4 * 4);
            float4 ko;
            ko.x = tf32r(kv.x); ko.y = tf32r(kv.y);
            ko.z = tf32r(kv.z); ko.w = tf32r(kv.w);
            *reinterpret_cast<float4*>(&Ks[row * 68 + c4 * 4]) = ko;
        }
        // stage V tile (fp16, [dim][key])
        #pragma unroll
        for (int i = 0; i < 4; i++) {
            const int u4 = i * 128 + threadIdx.x;       // 0..511
            const int d  = u4 >> 3, k8 = u4 & 7;
            uint4 vv = *reinterpret_cast<const uint4*>(vg + (size_t)d * 1024 + jt + k8 * 8);
            *reinterpret_cast<uint4*>(&Vt[d * 72 + k8 * 8]) = vv;
        }
        __syncthreads();

        // ---- S = Q K^T (tf32) ----
        float S[8][4];
        #pragma unroll
        for (int nt = 0; nt < 8; nt++) { S[nt][0] = S[nt][1] = S[nt][2] = S[nt][3] = 0.f; }
        #pragma unroll
        for (int nt = 0; nt < 8; nt++) {
            const float* kb = &Ks[(nt * 8 + g) * 68];
            #pragma unroll
            for (int ks = 0; ks < 8; ks++) {
                uint32_t b0 = __float_as_uint(kb[ks * 8 + t]);
                uint32_t b1 = __float_as_uint(kb[ks * 8 + t + 4]);
                mma_tf32(S[nt], Qfr[ks], b0, b1);
            }
        }

        // ---- mask out window |col-row|<=3 (only near-diagonal tiles) ----
        if (jt <= s0 + 66 && jt + 66 >= s0) {
            #pragma unroll
            for (int nt = 0; nt < 8; nt++) {
                const int c = jt + nt * 8 + 2 * t;
                if ((unsigned)(c     - r0 + WIN) <= 2u * WIN) S[nt][0] -= 1e9f;
                if ((unsigned)(c + 1 - r0 + WIN) <= 2u * WIN) S[nt][1] -= 1e9f;
                if ((unsigned)(c     - r1 + WIN) <= 2u * WIN) S[nt][2] -= 1e9f;
                if ((unsigned)(c + 1 - r1 + WIN) <= 2u * WIN) S[nt][3] -= 1e9f;
            }
        }

        // ---- online softmax (rows r0, r1 per thread; t-group shares row) ----
        float t0 = -1e30f, t1 = -1e30f;
        #pragma unroll
        for (int nt = 0; nt < 8; nt++) {
            t0 = fmaxf(t0, fmaxf(S[nt][0], S[nt][1]));
            t1 = fmaxf(t1, fmaxf(S[nt][2], S[nt][3]));
        }
        t0 = fmaxf(t0, __shfl_xor_sync(0xffffffffu, t0, 1));
        t0 = fmaxf(t0, __shfl_xor_sync(0xffffffffu, t0, 2));
        t1 = fmaxf(t1, __shfl_xor_sync(0xffffffffu, t1, 1));
        t1 = fmaxf(t1, __shfl_xor_sync(0xffffffffu, t1, 2));
        const float mn0 = fmaxf(m0r, t0), mn1 = fmaxf(m1r, t1);
        const float c0 = __expf(m0r - mn0), c1 = __expf(m1r - mn1);
        m0r = mn0; m1r = mn1;

        uint32_t Pf[4][4];
        float ps0 = 0.f, ps1 = 0.f;
        #pragma unroll
        for (int m = 0; m < 4; m++) {
            const int n0t = 2 * m, n1t = 2 * m + 1;
            float pa = __expf(S[n0t][0] - mn0), pb = __expf(S[n0t][1] - mn0);
            float pc = __expf(S[n0t][2] - mn1), pd = __expf(S[n0t][3] - mn1);
            float pe = __expf(S[n1t][0] - mn0), pf = __expf(S[n1t][1] - mn0);
            float pg = __expf(S[n1t][2] - mn1), ph = __expf(S[n1t][3] - mn1);
            ps0 += pa + pb + pe + pf;
            ps1 += pc + pd + pg + ph;
            Pf[m][0] = pack_h2(pa, pb);
            Pf[m][1] = pack_h2(pc, pd);
            Pf[m][2] = pack_h2(pe, pf);
            Pf[m][3] = pack_h2(pg, ph);
        }
        ps0 += __shfl_xor_sync(0xffffffffu, ps0, 1);
        ps0 += __shfl_xor_sync(0xffffffffu, ps0, 2);
        ps1 += __shfl_xor_sync(0xffffffffu, ps1, 1);
        ps1 += __shfl_xor_sync(0xffffffffu, ps1, 2);
        l0 = l0 * c0 + ps0;
        l1 = l1 * c1 + ps1;

        #pragma unroll
        for (int dn = 0; dn < 8; dn++) {
            O[dn][0] *= c0; O[dn][1] *= c0;
            O[dn][2] *= c1; O[dn][3] *= c1;
        }

        // ---- O += P V (fp16) ----
        #pragma unroll
        for (int m = 0; m < 4; m++) {
            #pragma unroll
            for (int dn = 0; dn < 8; dn++) {
                const __half* vb = &Vt[(dn * 8 + g) * 72 + m * 16 + 2 * t];
                uint32_t b0 = *reinterpret_cast<const uint32_t*>(vb);
                uint32_t b1 = *reinterpret_cast<const uint32_t*>(vb + 8);
                mma_f16(O[dn], Pf[m], b0, b1);
            }
        }
    }

    // ---- epilogue: normalize + store ----
    const float inv0 = 1.f / l0, inv1 = 1.f / l1;
    float* ob = g_ao + ((size_t)(b * Sn + s0 + w * 16)) * Cn + h * HDn;
    #pragma unroll
    for (int nt = 0; nt < 8; nt++) {
        float2 o0 = make_float2(O[nt][0] * inv0, O[nt][1] * inv0);
        float2 o1 = make_float2(O[nt][2] * inv1, O[nt][3] * inv1);
        *reinterpret_cast<float2*>(&ob[(size_t) g      * 256 + nt * 8 + 2 * t]) = o0;
        *reinterpret_cast<float2*>(&ob[(size_t)(g + 8) * 256 + nt * 8 + 2 * t]) = o1;
    }
}

// ---------------------------------------------------------------------------
// Output projection + reshape-scatter + residual (unchanged)
// ---------------------------------------------------------------------------
__global__ void oproj_kernel(const float* __restrict__ x,
                             const float* __restrict__ Wo,
                             const float* __restrict__ bo,
                             float* __restrict__ out)
{
    __shared__ float As[16][64];
    __shared__ float Bs[16][64];
    const int tid = threadIdx.y * 16 + threadIdx.x;
    const int m0  = blockIdx.y * 64;
    const int n0  = blockIdx.x * 64;
    const int lm = tid & 63;
    const int lk = tid >> 6;
    const int lrow = tid >> 2;
    const int lc4  = (tid & 3) * 4;
    float acc[4][4] = {};

    for (int k0 = 0; k0 < 256; k0 += 16) {
        float4 a4 = *reinterpret_cast<const float4*>(
            &g_ao[(size_t)(m0 + lrow) * 256 + k0 + lc4]);
        As[lc4 + 0][lrow] = a4.x;
        As[lc4 + 1][lrow] = a4.y;
        As[lc4 + 2][lrow] = a4.z;
        As[lc4 + 3][lrow] = a4.w;
        #pragma unroll
        for (int kk = lk; kk < 16; kk += 4)
            Bs[kk][lm] = Wo[(k0 + kk) * 256 + n0 + lm];
        __syncthreads();
        #pragma unroll
        for (int kk = 0; kk < 16; kk++) {
            float4 av = *reinterpret_cast<const float4*>(&As[kk][threadIdx.y * 4]);
            float4 bw = *reinterpret_cast<const float4*>(&Bs[kk][threadIdx.x * 4]);
            float a[4]  = {av.x, av.y, av.z, av.w};
            float b4[4] = {bw.x, bw.y, bw.z, bw.w};
            #pragma unroll
            for (int i = 0; i < 4; i++)
                #pragma unroll
                for (int j = 0; j < 4; j++)
                    acc[i][j] += a[i] * b4[j];
        }
        __syncthreads();
    }

    const int nbase = n0 + threadIdx.x * 4;
    const float4 br = *reinterpret_cast<const float4*>(&bo[nbase]);
    #pragma unroll
    for (int i = 0; i < 4; i++) {
        const int m  = m0 + threadIdx.y * 4 + i;
        const int bv = m >> 10;
        const int hw = m & 1023;
        const size_t flat = ((size_t)(bv * 256 + (hw >> 2))) * 1024
                          + (size_t)(hw & 3) * 256 + nbase;
        const float4 xr = *reinterpret_cast<const float4*>(&x[flat]);
        float4 o;
        o.x = acc[i][0] + br.x + xr.x;
        o.y = acc[i][1] + br.y + xr.y;
        o.z = acc[i][2] + br.z + xr.z;
        o.w = acc[i][3] + br.w + xr.w;
        *reinterpret_cast<float4*>(&out[flat]) = o;
    }
}

// ---------------------------------------------------------------------------
extern "C" void kernel_launch(void* const* d_in, const int* in_sizes, int n_in,
                              void* d_out, int out_size)
{
    const float* x  = (const float*)d_in[0];
    const float* Wq = (const float*)d_in[1];
    const float* bq = (const float*)d_in[2];
    const float* Wk = (const float*)d_in[3];
    const float* bk = (const float*)d_in[4];
    const float* Wv = (const float*)d_in[5];
    const float* bv = (const float*)d_in[6];
    const float* Wo = (const float*)d_in[7];
    const float* bo = (const float*)d_in[8];
    float* out = (float*)d_out;

    dim3 blk(16, 16);
    qproj_kernel <<<dim3(4, 384), blk>>>(x, Wq, bq);
    kvproj_kernel<<<dim3(4, 64),  blk>>>(x, Wk, bk, Wv, bv);
    attn_kernel  <<<dim3(96, 4, 4), 128>>>();
    oproj_kernel <<<dim3(4, 384), blk>>>(x, Wo, bo, out);
}

// round 3
// speedup vs baseline: 4.8757x; 1.8831x over previous
#include <cuda_runtime.h>
#include <cuda_fp16.h>
#include <cstdint>

// Problem constants
#define Bn   4
#define Vn   6
#define Cn   256
#define HWn  1024
#define Sn   6144      // Vn * HWn
#define NHn  4
#define HDn  64
#define WIN  3

// Scratch (allocation-free rule: __device__ globals)
__device__ float  g_q [(size_t)Bn * Sn  * Cn];    // 25.2 MB [B,S,C] fp32
__device__ __half g_kh[(size_t)Bn * HWn * Cn];    //  2.1 MB [B,HW,C] fp16
__device__ __half g_vt[(size_t)Bn * Cn  * HWn];   //  2.1 MB [B,C,HW] fp16 (transposed)
__device__ float  g_ao[(size_t)Bn * Sn  * Cn];    // 25.2 MB [B,S,C] fp32

// ---------------------------------------------------------------------------
// mma helpers
// ---------------------------------------------------------------------------
__device__ __forceinline__ void mma_tf32(float* d, const uint32_t* a,
                                         uint32_t b0, uint32_t b1)
{
    asm volatile(
        "mma.sync.aligned.m16n8k8.row.col.f32.tf32.tf32.f32 "
        "{%0,%1,%2,%3}, {%4,%5,%6,%7}, {%8,%9}, {%0,%1,%2,%3};"
        : "+f"(d[0]), "+f"(d[1]), "+f"(d[2]), "+f"(d[3])
        : "r"(a[0]), "r"(a[1]), "r"(a[2]), "r"(a[3]), "r"(b0), "r"(b1));
}

__device__ __forceinline__ void mma_f16(float* d, const uint32_t* a,
                                        uint32_t b0, uint32_t b1)
{
    asm volatile(
        "mma.sync.aligned.m16n8k16.row.col.f32.f16.f16.f32 "
        "{%0,%1,%2,%3}, {%4,%5,%6,%7}, {%8,%9}, {%0,%1,%2,%3};"
        : "+f"(d[0]), "+f"(d[1]), "+f"(d[2]), "+f"(d[3])
        : "r"(a[0]), "r"(a[1]), "r"(a[2]), "r"(a[3]), "r"(b0), "r"(b1));
}

__device__ __forceinline__ float tf32r(float x)
{
    uint32_t u;
    asm("cvt.rna.tf32.f32 %0, %1;" : "=r"(u) : "f"(x));
    return __uint_as_float(u);
}

__device__ __forceinline__ uint32_t pack_h2(float a, float b)
{
    __half2 h = __floats2half2_rn(a, b);
    return *reinterpret_cast<uint32_t*>(&h);
}

// SMEM strides (fp32 words / fp16 halves) chosen so (stride mod 32)=8 -> no conflicts
#define AS_STRIDE 136   // 128 + 8 floats
#define BS_STRIDE 72    // 64 + 8 floats
#define KV_STRIDE 72    // 64 + 8 halves

// ---------------------------------------------------------------------------
// Q projection (tf32 tensor cores): [24576 x 256] @ [256 x 256] + bq
// A^T contiguous in gmem: x[bv*C*HW + k*HW + hw]
// CTA tile 128m x 64n, 4 warps (each 32m x 64n), K chunks of 16.
// ---------------------------------------------------------------------------
__global__ void __launch_bounds__(128) qproj_kernel(
    const float* __restrict__ x,
    const float* __restrict__ Wq,
    const float* __restrict__ bq)
{
    __shared__ float As[16 * AS_STRIDE];
    __shared__ float Bs[16 * BS_STRIDE];
    const int tid  = threadIdx.x;
    const int w    = tid >> 5;
    const int lane = tid & 31;
    const int g = lane >> 2, t = lane & 3;
    const int m0 = blockIdx.y * 128;
    const int n0 = blockIdx.x * 64;
    const int bv  = m0 >> 10;
    const int hw0 = m0 & 1023;
    const float* abase = x + (size_t)bv * Cn * HWn + hw0;

    float acc[2][8][4] = {};

    for (int k0 = 0; k0 < 256; k0 += 16) {
        __syncthreads();
        #pragma unroll
        for (int i = 0; i < 4; i++) {              // As: 16 rows x 128, [k][m]
            const int idx = i * 128 + tid;
            const int row = idx >> 5, c4 = idx & 31;
            float4 a4 = *reinterpret_cast<const float4*>(
                abase + (size_t)(k0 + row) * HWn + c4 * 4);
            float* d = &As[row * AS_STRIDE + c4 * 4];
            d[0] = tf32r(a4.x); d[1] = tf32r(a4.y);
            d[2] = tf32r(a4.z); d[3] = tf32r(a4.w);
        }
        #pragma unroll
        for (int i = 0; i < 2; i++) {              // Bs: 16 rows x 64, [k][n]
            const int idx = i * 128 + tid;
            const int row = idx >> 4, c4 = idx & 15;
            float4 b4 = *reinterpret_cast<const float4*>(
                Wq + (size_t)(k0 + row) * 256 + n0 + c4 * 4);
            float* d = &Bs[row * BS_STRIDE + c4 * 4];
            d[0] = tf32r(b4.x); d[1] = tf32r(b4.y);
            d[2] = tf32r(b4.z); d[3] = tf32r(b4.w);
        }
        __syncthreads();

        #pragma unroll
        for (int kk = 0; kk < 2; kk++) {           // two k8 steps
            uint32_t afr[2][4];
            #pragma unroll
            for (int mb = 0; mb < 2; mb++) {
                const int mbase = w * 32 + mb * 16;
                afr[mb][0] = __float_as_uint(As[(kk*8 + t    ) * AS_STRIDE + mbase + g    ]);
                afr[mb][1] = __float_as_uint(As[(kk*8 + t    ) * AS_STRIDE + mbase + g + 8]);
                afr[mb][2] = __float_as_uint(As[(kk*8 + t + 4) * AS_STRIDE + mbase + g    ]);
                afr[mb][3] = __float_as_uint(As[(kk*8 + t + 4) * AS_STRIDE + mbase + g + 8]);
            }
            #pragma unroll
            for (int nt = 0; nt < 8; nt++) {
                uint32_t b0 = __float_as_uint(Bs[(kk*8 + t    ) * BS_STRIDE + nt*8 + g]);
                uint32_t b1 = __float_as_uint(Bs[(kk*8 + t + 4) * BS_STRIDE + nt*8 + g]);
                mma_tf32(acc[0][nt], afr[0], b0, b1);
                mma_tf32(acc[1][nt], afr[1], b0, b1);
            }
        }
    }

    #pragma unroll
    for (int mb = 0; mb < 2; mb++) {
        const int mr = m0 + w * 32 + mb * 16;
        #pragma unroll
        for (int nt = 0; nt < 8; nt++) {
            const int n = n0 + nt * 8 + 2 * t;
            const float2 bb = *reinterpret_cast<const float2*>(&bq[n]);
            float2 o0 = make_float2(acc[mb][nt][0] + bb.x, acc[mb][nt][1] + bb.y);
            float2 o1 = make_float2(acc[mb][nt][2] + bb.x, acc[mb][nt][3] + bb.y);
            *reinterpret_cast<float2*>(&g_q[(size_t)(mr + g    ) * 256 + n]) = o0;
            *reinterpret_cast<float2*>(&g_q[(size_t)(mr + g + 8) * 256 + n]) = o1;
        }
    }
}

// ---------------------------------------------------------------------------
// K and V projection (tf32 tensor cores, fused): [4096 x 1536] @ [1536 x 256]
// K -> g_kh fp16 [B,HW,C];  V -> g_vt fp16 transposed [B,C,HW]
// ---------------------------------------------------------------------------
__global__ void __launch_bounds__(128) kvproj_kernel(
    const float* __restrict__ x,
    const float* __restrict__ Wk,
    const float* __restrict__ bk,
    const float* __restrict__ Wv,
    const float* __restrict__ bvp)
{
    __shared__ float As [16 * AS_STRIDE];
    __shared__ float Bks[16 * BS_STRIDE];
    __shared__ float Bvs[16 * BS_STRIDE];
    const int tid  = threadIdx.x;
    const int w    = tid >> 5;
    const int lane = tid & 31;
    const int g = lane >> 2, t = lane & 3;
    const int m0 = blockIdx.y * 128;
    const int n0 = blockIdx.x * 64;
    const int b   = m0 >> 10;
    const int hw0 = m0 & 1023;

    float acck[2][8][4] = {};
    float accv[2][8][4] = {};

    for (int k0 = 0; k0 < 1536; k0 += 16) {
        __syncthreads();
        #pragma unroll
        for (int i = 0; i < 4; i++) {
            const int idx = i * 128 + tid;
            const int row = idx >> 5, c4 = idx & 31;
            const int kg = k0 + row;
            const int vv = kg >> 8, cc = kg & 255;
            float4 a4 = *reinterpret_cast<const float4*>(
                x + ((size_t)(b * Vn + vv) * Cn + cc) * HWn + hw0 + c4 * 4);
            float* d = &As[row * AS_STRIDE + c4 * 4];
            d[0] = tf32r(a4.x); d[1] = tf32r(a4.y);
            d[2] = tf32r(a4.z); d[3] = tf32r(a4.w);
        }
        #pragma unroll
        for (int i = 0; i < 2; i++) {
            const int idx = i * 128 + tid;
            const int row = idx >> 4, c4 = idx & 15;
            float4 k4 = *reinterpret_cast<const float4*>(
                Wk + (size_t)(k0 + row) * 256 + n0 + c4 * 4);
            float4 v4 = *reinterpret_cast<const float4*>(
                Wv + (size_t)(k0 + row) * 256 + n0 + c4 * 4);
            float* dk = &Bks[row * BS_STRIDE + c4 * 4];
            float* dv = &Bvs[row * BS_STRIDE + c4 * 4];
            dk[0] = tf32r(k4.x); dk[1] = tf32r(k4.y);
            dk[2] = tf32r(k4.z); dk[3] = tf32r(k4.w);
            dv[0] = tf32r(v4.x); dv[1] = tf32r(v4.y);
            dv[2] = tf32r(v4.z); dv[3] = tf32r(v4.w);
        }
        __syncthreads();

        #pragma unroll
        for (int kk = 0; kk < 2; kk++) {
            uint32_t afr[2][4];
            #pragma unroll
            for (int mb = 0; mb < 2; mb++) {
                const int mbase = w * 32 + mb * 16;
                afr[mb][0] = __float_as_uint(As[(kk*8 + t    ) * AS_STRIDE + mbase + g    ]);
                afr[mb][1] = __float_as_uint(As[(kk*8 + t    ) * AS_STRIDE + mbase + g + 8]);
                afr[mb][2] = __float_as_uint(As[(kk*8 + t + 4) * AS_STRIDE + mbase + g    ]);
                afr[mb][3] = __float_as_uint(As[(kk*8 + t + 4) * AS_STRIDE + mbase + g + 8]);
            }
            #pragma unroll
            for (int nt = 0; nt < 8; nt++) {
                uint32_t bk0 = __float_as_uint(Bks[(kk*8 + t    ) * BS_STRIDE + nt*8 + g]);
                uint32_t bk1 = __float_as_uint(Bks[(kk*8 + t + 4) * BS_STRIDE + nt*8 + g]);
                uint32_t bv0 = __float_as_uint(Bvs[(kk*8 + t    ) * BS_STRIDE + nt*8 + g]);
                uint32_t bv1 = __float_as_uint(Bvs[(kk*8 + t + 4) * BS_STRIDE + nt*8 + g]);
                mma_tf32(acck[0][nt], afr[0], bk0, bk1);
                mma_tf32(acck[1][nt], afr[1], bk0, bk1);
                mma_tf32(accv[0][nt], afr[0], bv0, bv1);
                mma_tf32(accv[1][nt], afr[1], bv0, bv1);
            }
        }
    }

    #pragma unroll
    for (int mb = 0; mb < 2; mb++) {
        const int mr = m0 + w * 32 + mb * 16;
        #pragma unroll
        for (int nt = 0; nt < 8; nt++) {
            const int n = n0 + nt * 8 + 2 * t;
            const float2 bbk = *reinterpret_cast<const float2*>(&bk [n]);
            const float2 bbv = *reinterpret_cast<const float2*>(&bvp[n]);
            #pragma unroll
            for (int rr = 0; rr < 2; rr++) {
                const int m  = mr + g + rr * 8;
                const int hw = m & 1023;
                // K: fp16 row-major [B,HW,C]
                __half2 kh = __floats2half2_rn(acck[mb][nt][2*rr]   + bbk.x,
                                               acck[mb][nt][2*rr+1] + bbk.y);
                *reinterpret_cast<__half2*>(
                    &g_kh[((size_t)(b * HWn + hw)) * 256 + n]) = kh;
                // V: fp16 transposed [B,C,HW]
                g_vt[(((size_t)(b * 256 + n    )) << 10) + hw] =
                    __float2half(accv[mb][nt][2*rr]   + bbv.x);
                g_vt[(((size_t)(b * 256 + n + 1)) << 10) + hw] =
                    __float2half(accv[mb][nt][2*rr+1] + bbv.y);
            }
        }
    }
}

// ---------------------------------------------------------------------------
// Flash attention, all-fp16 mma: QK^T (m16n8k16) + PV (m16n8k16).
// CTA = 128 queries (8 warps x m16); K tiles of 64 keys.
// Ks smem [key][dim] fp16; Vt smem [dim][key] fp16. Online softmax.
// ---------------------------------------------------------------------------
__global__ void __launch_bounds__(256) attn_kernel()
{
    __shared__ __half Ks[64 * KV_STRIDE];   // [key][dim]
    __shared__ __half Vt[64 * KV_STRIDE];   // [dim][key]

    const int b  = blockIdx.z;
    const int h  = blockIdx.y;
    const int s0 = blockIdx.x * 128;
    const int w    = threadIdx.x >> 5;
    const int lane = threadIdx.x & 31;
    const int g = lane >> 2;
    const int t = lane & 3;

    // Q fragments (fp16, scale folded): rows s0+16w+{g,g+8}
    const float* qbase = g_q + ((size_t)(b * Sn + s0 + w * 16)) * Cn + h * HDn;
    uint32_t Qfr[4][4];
    #pragma unroll
    for (int ks = 0; ks < 4; ks++) {
        const int d0 = ks * 16 + 2 * t;
        float2 qa = *reinterpret_cast<const float2*>(&qbase[(size_t) g      * 256 + d0    ]);
        float2 qb = *reinterpret_cast<const float2*>(&qbase[(size_t)(g + 8) * 256 + d0    ]);
        float2 qc = *reinterpret_cast<const float2*>(&qbase[(size_t) g      * 256 + d0 + 8]);
        float2 qd = *reinterpret_cast<const float2*>(&qbase[(size_t)(g + 8) * 256 + d0 + 8]);
        Qfr[ks][0] = pack_h2(qa.x * 0.125f, qa.y * 0.125f);
        Qfr[ks][1] = pack_h2(qb.x * 0.125f, qb.y * 0.125f);
        Qfr[ks][2] = pack_h2(qc.x * 0.125f, qc.y * 0.125f);
        Qfr[ks][3] = pack_h2(qd.x * 0.125f, qd.y * 0.125f);
    }

    float O[8][4];
    #pragma unroll
    for (int i = 0; i < 8; i++) { O[i][0] = O[i][1] = O[i][2] = O[i][3] = 0.f; }
    float m0r = -1e30f, m1r = -1e30f, l0 = 0.f, l1 = 0.f;

    const __half* kg = g_kh + ((size_t)b * HWn) * 256 + h * HDn;        // row stride 256
    const __half* vg = g_vt + (((size_t)(b * 256 + h * 64)) << 10);     // row stride 1024

    const int r0 = s0 + w * 16 + g;
    const int r1 = r0 + 8;

    for (int jt = 0; jt < HWn; jt += 64) {
        __syncthreads();
        // stage K tile: Ks[key][dim]
        #pragma unroll
        for (int i = 0; i < 2; i++) {
            const int idx = i * 256 + threadIdx.x;     // 0..511
            const int row = idx >> 3, h8 = idx & 7;
            uint4 kk = *reinterpret_cast<const uint4*>(
                kg + (size_t)(jt + row) * 256 + h8 * 8);
            *reinterpret_cast<uint4*>(&Ks[row * KV_STRIDE + h8 * 8]) = kk;
        }
        // stage V tile: Vt[dim][key]
        #pragma unroll
        for (int i = 0; i < 2; i++) {
            const int idx = i * 256 + threadIdx.x;
            const int d = idx >> 3, k8 = idx & 7;
            uint4 vv = *reinterpret_cast<const uint4*>(
                vg + (size_t)d * 1024 + jt + k8 * 8);
            *reinterpret_cast<uint4*>(&Vt[d * KV_STRIDE + k8 * 8]) = vv;
        }
        __syncthreads();

        // ---- S = Q K^T (fp16) ----
        float S[8][4];
        #pragma unroll
        for (int nt = 0; nt < 8; nt++) { S[nt][0] = S[nt][1] = S[nt][2] = S[nt][3] = 0.f; }
        #pragma unroll
        for (int nt = 0; nt < 8; nt++) {
            const __half* kb = &Ks[(nt * 8 + g) * KV_STRIDE];
            #pragma unroll
            for (int ks = 0; ks < 4; ks++) {
                uint32_t b0 = *reinterpret_cast<const uint32_t*>(&kb[ks * 16 + 2 * t    ]);
                uint32_t b1 = *reinterpret_cast<const uint32_t*>(&kb[ks * 16 + 2 * t + 8]);
                mma_f16(S[nt], Qfr[ks], b0, b1);
            }
        }

        // ---- mask |col-row|<=WIN ----
        if (jt <= s0 + 130 && jt + 66 >= s0) {
            #pragma unroll
            for (int nt = 0; nt < 8; nt++) {
                const int c = jt + nt * 8 + 2 * t;
                if ((unsigned)(c     - r0 + WIN) <= 2u * WIN) S[nt][0] -= 1e9f;
                if ((unsigned)(c + 1 - r0 + WIN) <= 2u * WIN) S[nt][1] -= 1e9f;
                if ((unsigned)(c     - r1 + WIN) <= 2u * WIN) S[nt][2] -= 1e9f;
                if ((unsigned)(c + 1 - r1 + WIN) <= 2u * WIN) S[nt][3] -= 1e9f;
            }
        }

        // ---- online softmax ----
        float t0 = -1e30f, t1 = -1e30f;
        #pragma unroll
        for (int nt = 0; nt < 8; nt++) {
            t0 = fmaxf(t0, fmaxf(S[nt][0], S[nt][1]));
            t1 = fmaxf(t1, fmaxf(S[nt][2], S[nt][3]));
        }
        t0 = fmaxf(t0, __shfl_xor_sync(0xffffffffu, t0, 1));
        t0 = fmaxf(t0, __shfl_xor_sync(0xffffffffu, t0, 2));
        t1 = fmaxf(t1, __shfl_xor_sync(0xffffffffu, t1, 1));
        t1 = fmaxf(t1, __shfl_xor_sync(0xffffffffu, t1, 2));
        const float mn0 = fmaxf(m0r, t0), mn1 = fmaxf(m1r, t1);
        const float c0 = __expf(m0r - mn0), c1 = __expf(m1r - mn1);
        m0r = mn0; m1r = mn1;

        uint32_t Pf[4][4];
        float ps0 = 0.f, ps1 = 0.f;
        #pragma unroll
        for (int m = 0; m < 4; m++) {
            const int n0t = 2 * m, n1t = 2 * m + 1;
            float pa = __expf(S[n0t][0] - mn0), pb = __expf(S[n0t][1] - mn0);
            float pc = __expf(S[n0t][2] - mn1), pd = __expf(S[n0t][3] - mn1);
            float pe = __expf(S[n1t][0] - mn0), pf = __expf(S[n1t][1] - mn0);
            float pg = __expf(S[n1t][2] - mn1), ph = __expf(S[n1t][3] - mn1);
            ps0 += pa + pb + pe + pf;
            ps1 += pc + pd + pg + ph;
            Pf[m][0] = pack_h2(pa, pb);
            Pf[m][1] = pack_h2(pc, pd);
            Pf[m][2] = pack_h2(pe, pf);
            Pf[m][3] = pack_h2(pg, ph);
        }
        ps0 += __shfl_xor_sync(0xffffffffu, ps0, 1);
        ps0 += __shfl_xor_sync(0xffffffffu, ps0, 2);
        ps1 += __shfl_xor_sync(0xffffffffu, ps1, 1);
        ps1 += __shfl_xor_sync(0xffffffffu, ps1, 2);
        l0 = l0 * c0 + ps0;
        l1 = l1 * c1 + ps1;

        #pragma unroll
        for (int dn = 0; dn < 8; dn++) {
            O[dn][0] *= c0; O[dn][1] *= c0;
            O[dn][2] *= c1; O[dn][3] *= c1;
        }

        // ---- O += P V ----
        #pragma unroll
        for (int m = 0; m < 4; m++) {
            #pragma unroll
            for (int dn = 0; dn < 8; dn++) {
                const __half* vb = &Vt[(dn * 8 + g) * KV_STRIDE + m * 16 + 2 * t];
                uint32_t b0 = *reinterpret_cast<const uint32_t*>(vb);
                uint32_t b1 = *reinterpret_cast<const uint32_t*>(vb + 8);
                mma_f16(O[dn], Pf[m], b0, b1);
            }
        }
    }

    // ---- epilogue ----
    const float inv0 = 1.f / l0, inv1 = 1.f / l1;
    float* ob = g_ao + ((size_t)(b * Sn + s0 + w * 16)) * Cn + h * HDn;
    #pragma unroll
    for (int nt = 0; nt < 8; nt++) {
        float2 o0 = make_float2(O[nt][0] * inv0, O[nt][1] * inv0);
        float2 o1 = make_float2(O[nt][2] * inv1, O[nt][3] * inv1);
        *reinterpret_cast<float2*>(&ob[(size_t) g      * 256 + nt * 8 + 2 * t]) = o0;
        *reinterpret_cast<float2*>(&ob[(size_t)(g + 8) * 256 + nt * 8 + 2 * t]) = o1;
    }
}

// ---------------------------------------------------------------------------
// Output projection (tf32 tensor cores) + reshape-scatter + residual.
// A = g_ao row-major [M,256] (transposed into SMEM during staging).
// out flat = ((bv*256 + (hw>>2))*1024 + (hw&3)*256 + n;  out = Y + x[flat]
// ---------------------------------------------------------------------------
__global__ void __launch_bounds__(128) oproj_kernel(
    const float* __restrict__ x,
    const float* __restrict__ Wo,
    const float* __restrict__ bo,
    float* __restrict__ out)
{
    __shared__ float As[16 * AS_STRIDE];
    __shared__ float Bs[16 * BS_STRIDE];
    const int tid  = threadIdx.x;
    const int w    = tid >> 5;
    const int lane = tid & 31;
    const int g = lane >> 2, t = lane & 3;
    const int m0 = blockIdx.y * 128;
    const int n0 = blockIdx.x * 64;

    float acc[2][8][4] = {};

    for (int k0 = 0; k0 < 256; k0 += 16) {
        __syncthreads();
        #pragma unroll
        for (int i = 0; i < 4; i++) {   // transpose-stage A: row m=tid, k chunk i*4
            float4 a4 = *reinterpret_cast<const float4*>(
                &g_ao[(size_t)(m0 + tid) * 256 + k0 + i * 4]);
            As[(i*4 + 0) * AS_STRIDE + tid] = tf32r(a4.x);
            As[(i*4 + 1) * AS_STRIDE + tid] = tf32r(a4.y);
            As[(i*4 + 2) * AS_STRIDE + tid] = tf32r(a4.z);
            As[(i*4 + 3) * AS_STRIDE + tid] = tf32r(a4.w);
        }
        #pragma unroll
        for (int i = 0; i < 2; i++) {
            const int idx = i * 128 + tid;
            const int row = idx >> 4, c4 = idx & 15;
            float4 b4 = *reinterpret_cast<const float4*>(
                Wo + (size_t)(k0 + row) * 256 + n0 + c4 * 4);
            float* d = &Bs[row * BS_STRIDE + c4 * 4];
            d[0] = tf32r(b4.x); d[1] = tf32r(b4.y);
            d[2] = tf32r(b4.z); d[3] = tf32r(b4.w);
        }
        __syncthreads();

        #pragma unroll
        for (int kk = 0; kk < 2; kk++) {
            uint32_t afr[2][4];
            #pragma unroll
            for (int mb = 0; mb < 2; mb++) {
                const int mbase = w * 32 + mb * 16;
                afr[mb][0] = __float_as_uint(As[(kk*8 + t    ) * AS_STRIDE + mbase + g    ]);
                afr[mb][1] = __float_as_uint(As[(kk*8 + t    ) * AS_STRIDE + mbase + g + 8]);
                afr[mb][2] = __float_as_uint(As[(kk*8 + t + 4) * AS_STRIDE + mbase + g    ]);
                afr[mb][3] = __float_as_uint(As[(kk*8 + t + 4) * AS_STRIDE + mbase + g + 8]);
            }
            #pragma unroll
            for (int nt = 0; nt < 8; nt++) {
                uint32_t b0 = __float_as_uint(Bs[(kk*8 + t    ) * BS_STRIDE + nt*8 + g]);
                uint32_t b1 = __float_as_uint(Bs[(kk*8 + t + 4) * BS_STRIDE + nt*8 + g]);
                mma_tf32(acc[0][nt], afr[0], b0, b1);
                mma_tf32(acc[1][nt], afr[1], b0, b1);
            }
        }
    }

    #pragma unroll
    for (int mb = 0; mb < 2; mb++) {
        const int mr = m0 + w * 32 + mb * 16;
        #pragma unroll
        for (int nt = 0; nt < 8; nt++) {
            const int n = n0 + nt * 8 + 2 * t;
            const float2 bb = *reinterpret_cast<const float2*>(&bo[n]);
            #pragma unroll
            for (int rr = 0; rr < 2; rr++) {
                const int m  = mr + g + rr * 8;
                const int bv = m >> 10;
                const int hw = m & 1023;
                const size_t flat = ((size_t)(bv * 256 + (hw >> 2))) * 1024
                                  + (size_t)(hw & 3) * 256 + n;
                const float2 xr = *reinterpret_cast<const float2*>(&x[flat]);
                float2 o;
                o.x = acc[mb][nt][2*rr]   + bb.x + xr.x;
                o.y = acc[mb][nt][2*rr+1] + bb.y + xr.y;
                *reinterpret_cast<float2*>(&out[flat]) = o;
            }
        }
    }
}

// ---------------------------------------------------------------------------
extern "C" void kernel_launch(void* const* d_in, const int* in_sizes, int n_in,
                              void* d_out, int out_size)
{
    const float* x  = (const float*)d_in[0];
    const float* Wq = (const float*)d_in[1];
    const float* bq = (const float*)d_in[2];
    const float* Wk = (const float*)d_in[3];
    const float* bk = (const float*)d_in[4];
    const float* Wv = (const float*)d_in[5];
    const float* bv = (const float*)d_in[6];
    const float* Wo = (const float*)d_in[7];
    const float* bo = (const float*)d_in[8];
    float* out = (float*)d_out;

    qproj_kernel <<<dim3(4, 192), 128>>>(x, Wq, bq);
    kvproj_kernel<<<dim3(4, 32),  128>>>(x, Wk, bk, Wv, bv);
    attn_kernel  <<<dim3(48, 4, 4), 256>>>();
    oproj_kernel <<<dim3(4, 192), 128>>>(x, Wo, bo, out);
}

// round 5
// speedup vs baseline: 7.9877x; 1.6383x over previous
#include <cuda_runtime.h>
#include <cuda_fp16.h>
#include <cstdint>

// Problem constants
#define Bn   4
#define Vn   6
#define Cn   256
#define HWn  1024
#define Sn   6144
#define WIN  3
#define QSCALE (0.125f * 1.44269504f)   // 1/sqrt(64) * log2(e)

// Scratch (__device__ globals; allocation-free rule)
__device__ __half g_xt [(size_t)Bn * Vn * HWn * Cn];  // [bv][hw][c]
__device__ __half g_qh [(size_t)Bn * Sn  * Cn];       // [B,S,C]  (scaled by QSCALE)
__device__ __half g_kh [(size_t)Bn * HWn * Cn];       // [B,HW,C]
__device__ __half g_vt [(size_t)Bn * Cn  * HWn];      // [B,C,HW] (transposed)
__device__ __half g_aoh[(size_t)Bn * Sn  * Cn];       // [B,S,C]
__device__ __half g_wqt[256 * 256];                   // W^T [n][k]
__device__ __half g_wkt[256 * 1536];
__device__ __half g_wvt[256 * 1536];
__device__ __half g_wot[256 * 256];

// ---------------------------------------------------------------------------
// helpers
// ---------------------------------------------------------------------------
__device__ __forceinline__ void mma_f16(float* d, const uint32_t* a,
                                        uint32_t b0, uint32_t b1)
{
    asm volatile(
        "mma.sync.aligned.m16n8k16.row.col.f32.f16.f16.f32 "
        "{%0,%1,%2,%3}, {%4,%5,%6,%7}, {%8,%9}, {%0,%1,%2,%3};"
        : "+f"(d[0]), "+f"(d[1]), "+f"(d[2]), "+f"(d[3])
        : "r"(a[0]), "r"(a[1]), "r"(a[2]), "r"(a[3]), "r"(b0), "r"(b1));
}

__device__ __forceinline__ uint32_t pack_h2(float a, float b)
{
    __half2 h = __floats2half2_rn(a, b);
    return *reinterpret_cast<uint32_t*>(&h);
}

__device__ __forceinline__ uint32_t h2exp2u(uint32_t x)
{
    __half2 h = h2exp2(*reinterpret_cast<__half2*>(&x));
    return *reinterpret_cast<uint32_t*>(&h);
}

__device__ __forceinline__ void cpa16(__half* dst, const __half* src)
{
    uint32_t s = (uint32_t)__cvta_generic_to_shared(dst);
    asm volatile("cp.async.cg.shared.global [%0], [%1], 16;" :: "r"(s), "l"(src));
}
#define CP_COMMIT() asm volatile("cp.async.commit_group;")
#define CP_WAIT1()  asm volatile("cp.async.wait_group 1;")

#define ASTR 40     // halves per A smem row (32 k + 8 pad)
#define BSTR 40
#define KVS  72     // halves per KV smem row (64 + 8 pad)

// ---------------------------------------------------------------------------
// prep: transpose x -> fp16 [bv][hw][c]
// ---------------------------------------------------------------------------
__global__ void prep_x(const float* __restrict__ x)
{
    __shared__ float ts[32][33];
    const int hw0 = blockIdx.x * 32, c0 = blockIdx.y * 32, bv = blockIdx.z;
    const int tx = threadIdx.x, ty = threadIdx.y;
    #pragma unroll
    for (int r = 0; r < 4; r++) {
        const int c = c0 + ty * 4 + r;
        ts[ty * 4 + r][tx] = x[((size_t)bv * 256 + c) * 1024 + hw0 + tx];
    }
    __syncthreads();
    #pragma unroll
    for (int r = 0; r < 4; r++) {
        const int hw = hw0 + ty * 4 + r;
        g_xt[((size_t)bv * 1024 + hw) * 256 + c0 + tx] = __float2half(ts[tx][ty * 4 + r]);
    }
}

// prep: weights W [K][256] -> W^T fp16 [256][K]
__global__ void prep_w(const float* __restrict__ Wq, const float* __restrict__ Wk,
                       const float* __restrict__ Wv, const float* __restrict__ Wo)
{
    const float* src; __half* dst; int K;
    switch (blockIdx.z) {
        case 0:  src = Wq; dst = g_wqt; K = 256;  break;
        case 1:  src = Wk; dst = g_wkt; K = 1536; break;
        case 2:  src = Wv; dst = g_wvt; K = 1536; break;
        default: src = Wo; dst = g_wot; K = 256;  break;
    }
    const int k0 = blockIdx.y * 32;
    if (k0 >= K) return;
    const int n0 = blockIdx.x * 32;
    const int tx = threadIdx.x, ty = threadIdx.y;
    __shared__ float ts[32][33];
    #pragma unroll
    for (int r = 0; r < 4; r++)
        ts[ty * 4 + r][tx] = src[(size_t)(k0 + ty * 4 + r) * 256 + n0 + tx];
    __syncthreads();
    #pragma unroll
    for (int r = 0; r < 4; r++)
        dst[(size_t)(n0 + ty * 4 + r) * K + k0 + tx] = __float2half(ts[tx][ty * 4 + r]);
}

// ---------------------------------------------------------------------------
// Q projection: fp16 GEMM [24576 x 256] @ Wq + bq, scaled by QSCALE -> g_qh
// CTA 128m x 64n, 256 thr (8 warps, warp 32m x 32n), K-chunks of 32, cp.async x2
// ---------------------------------------------------------------------------
__global__ void __launch_bounds__(256) qproj_kernel(const float* __restrict__ bq)
{
    __shared__ __align__(16) __half As[2][128 * ASTR];
    __shared__ __align__(16) __half Bs[2][64 * BSTR];
    const int tid = threadIdx.x;
    const int w = tid >> 5, lane = tid & 31, g = lane >> 2, t = lane & 3;
    const int wm = w >> 1, wn = w & 1;
    const int m0 = blockIdx.y * 128, n0 = blockIdx.x * 64;
    const __half* Ag = g_xt + (size_t)m0 * 256;
    const __half* Bg = g_wqt + (size_t)n0 * 256;

    const int ar0 = tid >> 2,           ac0 = (tid & 3) * 8;
    const int ar1 = (tid + 256) >> 2,   ac1 = ac0;
    const int br  = tid >> 2,           bc  = (tid & 3) * 8;

    #pragma unroll
    for (int pc = 0; pc < 2; pc++) {
        cpa16(&As[pc][ar0 * ASTR + ac0], Ag + (size_t)ar0 * 256 + pc * 32 + ac0);
        cpa16(&As[pc][ar1 * ASTR + ac1], Ag + (size_t)ar1 * 256 + pc * 32 + ac1);
        cpa16(&Bs[pc][br * BSTR + bc],   Bg + (size_t)br * 256 + pc * 32 + bc);
        CP_COMMIT();
    }

    float acc[2][4][4] = {};
    for (int kc = 0; kc < 8; kc++) {
        CP_WAIT1();
        __syncthreads();
        const __half* Ab = As[kc & 1];
        const __half* Bb = Bs[kc & 1];
        #pragma unroll
        for (int ks = 0; ks < 2; ks++) {
            uint32_t a[2][4], bb[4][2];
            #pragma unroll
            for (int mt = 0; mt < 2; mt++) {
                const int r = wm * 32 + mt * 16 + g;
                a[mt][0] = *(const uint32_t*)(Ab + (r    ) * ASTR + ks * 16 + 2 * t);
                a[mt][1] = *(const uint32_t*)(Ab + (r + 8) * ASTR + ks * 16 + 2 * t);
                a[mt][2] = *(const uint32_t*)(Ab + (r    ) * ASTR + ks * 16 + 2 * t + 8);
                a[mt][3] = *(const uint32_t*)(Ab + (r + 8) * ASTR + ks * 16 + 2 * t + 8);
            }
            #pragma unroll
            for (int nt = 0; nt < 4; nt++) {
                const int r = wn * 32 + nt * 8 + g;
                bb[nt][0] = *(const uint32_t*)(Bb + r * BSTR + ks * 16 + 2 * t);
                bb[nt][1] = *(const uint32_t*)(Bb + r * BSTR + ks * 16 + 2 * t + 8);
            }
            #pragma unroll
            for (int mt = 0; mt < 2; mt++)
                #pragma unroll
                for (int nt = 0; nt < 4; nt++)
                    mma_f16(acc[mt][nt], a[mt], bb[nt][0], bb[nt][1]);
        }
        __syncthreads();
        if (kc + 2 < 8) {
            const int nk = kc + 2, buf = kc & 1;
            cpa16(&As[buf][ar0 * ASTR + ac0], Ag + (size_t)ar0 * 256 + nk * 32 + ac0);
            cpa16(&As[buf][ar1 * ASTR + ac1], Ag + (size_t)ar1 * 256 + nk * 32 + ac1);
            cpa16(&Bs[buf][br * BSTR + bc],   Bg + (size_t)br * 256 + nk * 32 + bc);
        }
        CP_COMMIT();
    }

    #pragma unroll
    for (int mt = 0; mt < 2; mt++) {
        const int row0 = m0 + wm * 32 + mt * 16 + g;
        #pragma unroll
        for (int nt = 0; nt < 4; nt++) {
            const int n = n0 + wn * 32 + nt * 8 + 2 * t;
            const float2 bb = *reinterpret_cast<const float2*>(&bq[n]);
            __half2 h0 = __floats2half2_rn((acc[mt][nt][0] + bb.x) * QSCALE,
                                           (acc[mt][nt][1] + bb.y) * QSCALE);
            __half2 h1 = __floats2half2_rn((acc[mt][nt][2] + bb.x) * QSCALE,
                                           (acc[mt][nt][3] + bb.y) * QSCALE);
            *reinterpret_cast<__half2*>(&g_qh[(size_t) row0      * 256 + n]) = h0;
            *reinterpret_cast<__half2*>(&g_qh[(size_t)(row0 + 8) * 256 + n]) = h1;
        }
    }
}

// ---------------------------------------------------------------------------
// K/V projection (fused): [4096 x 1536] @ {Wk,Wv}; K -> g_kh, V -> g_vt
// ---------------------------------------------------------------------------
__global__ void __launch_bounds__(256) kvproj_kernel(const float* __restrict__ bk,
                                                     const float* __restrict__ bv)
{
    __shared__ __align__(16) __half As [2][128 * ASTR];
    __shared__ __align__(16) __half Bks[2][64 * BSTR];
    __shared__ __align__(16) __half Bvs[2][64 * BSTR];
    const int tid = threadIdx.x;
    const int w = tid >> 5, lane = tid & 31, g = lane >> 2, t = lane & 3;
    const int wm = w >> 1, wn = w & 1;
    const int m0 = blockIdx.y * 128, n0 = blockIdx.x * 64;
    const int bidx = m0 >> 10, hw0 = m0 & 1023;

    const int ar0 = tid >> 2,         ac0 = (tid & 3) * 8;
    const int ar1 = (tid + 256) >> 2, ac1 = ac0;
    const int br  = tid >> 2,         bc  = (tid & 3) * 8;

    #pragma unroll
    for (int pc = 0; pc < 2; pc++) {
        const int k0 = pc * 32, v = k0 >> 8, c0 = k0 & 255;
        const __half* Ag = g_xt + ((size_t)(bidx * Vn + v) * 1024 + hw0) * 256 + c0;
        cpa16(&As[pc][ar0 * ASTR + ac0], Ag + (size_t)ar0 * 256 + ac0);
        cpa16(&As[pc][ar1 * ASTR + ac1], Ag + (size_t)ar1 * 256 + ac1);
        cpa16(&Bks[pc][br * BSTR + bc], g_wkt + (size_t)(n0 + br) * 1536 + k0 + bc);
        cpa16(&Bvs[pc][br * BSTR + bc], g_wvt + (size_t)(n0 + br) * 1536 + k0 + bc);
        CP_COMMIT();
    }

    float acck[2][4][4] = {};
    float accv[2][4][4] = {};
    for (int kc = 0; kc < 48; kc++) {
        CP_WAIT1();
        __syncthreads();
        const __half* Ab  = As [kc & 1];
        const __half* Bkb = Bks[kc & 1];
        const __half* Bvb = Bvs[kc & 1];
        #pragma unroll
        for (int ks = 0; ks < 2; ks++) {
            uint32_t a[2][4], bkf[4][2], bvf[4][2];
            #pragma unroll
            for (int mt = 0; mt < 2; mt++) {
                const int r = wm * 32 + mt * 16 + g;
                a[mt][0] = *(const uint32_t*)(Ab + (r    ) * ASTR + ks * 16 + 2 * t);
                a[mt][1] = *(const uint32_t*)(Ab + (r + 8) * ASTR + ks * 16 + 2 * t);
                a[mt][2] = *(const uint32_t*)(Ab + (r    ) * ASTR + ks * 16 + 2 * t + 8);
                a[mt][3] = *(const uint32_t*)(Ab + (r + 8) * ASTR + ks * 16 + 2 * t + 8);
            }
            #pragma unroll
            for (int nt = 0; nt < 4; nt++) {
                const int r = wn * 32 + nt * 8 + g;
                bkf[nt][0] = *(const uint32_t*)(Bkb + r * BSTR + ks * 16 + 2 * t);
                bkf[nt][1] = *(const uint32_t*)(Bkb + r * BSTR + ks * 16 + 2 * t + 8);
                bvf[nt][0] = *(const uint32_t*)(Bvb + r * BSTR + ks * 16 + 2 * t);
                bvf[nt][1] = *(const uint32_t*)(Bvb + r * BSTR + ks * 16 + 2 * t + 8);
            }
            #pragma unroll
            for (int mt = 0; mt < 2; mt++)
                #pragma unroll
                for (int nt = 0; nt < 4; nt++) {
                    mma_f16(acck[mt][nt], a[mt], bkf[nt][0], bkf[nt][1]);
                    mma_f16(accv[mt][nt], a[mt], bvf[nt][0], bvf[nt][1]);
                }
        }
        __syncthreads();
        if (kc + 2 < 48) {
            const int nk = kc + 2, buf = kc & 1;
            const int k0 = nk * 32, v = k0 >> 8, c0 = k0 & 255;
            const __half* Ag = g_xt + ((size_t)(bidx * Vn + v) * 1024 + hw0) * 256 + c0;
            cpa16(&As[buf][ar0 * ASTR + ac0], Ag + (size_t)ar0 * 256 + ac0);
            cpa16(&As[buf][ar1 * ASTR + ac1], Ag + (size_t)ar1 * 256 + ac1);
            cpa16(&Bks[buf][br * BSTR + bc], g_wkt + (size_t)(n0 + br) * 1536 + k0 + bc);
            cpa16(&Bvs[buf][br * BSTR + bc], g_wvt + (size_t)(n0 + br) * 1536 + k0 + bc);
        }
        CP_COMMIT();
    }

    #pragma unroll
    for (int mt = 0; mt < 2; mt++) {
        const int row0 = m0 + wm * 32 + mt * 16 + g;
        #pragma unroll
        for (int nt = 0; nt < 4; nt++) {
            const int n = n0 + wn * 32 + nt * 8 + 2 * t;
            const float2 bbk = *reinterpret_cast<const float2*>(&bk[n]);
            const float2 bbv = *reinterpret_cast<const float2*>(&bv[n]);
            #pragma unroll
            for (int rr = 0; rr < 2; rr++) {
                const int r  = row0 + rr * 8;
                const int hw = r & 1023, bb = r >> 10;
                __half2 kh = __floats2half2_rn(acck[mt][nt][2*rr]   + bbk.x,
                                               acck[mt][nt][2*rr+1] + bbk.y);
                *reinterpret_cast<__half2*>(
                    &g_kh[((size_t)(bb * 1024 + hw)) * 256 + n]) = kh;
                g_vt[(((size_t)(bb * 256 + n    )) << 10) + hw] =
                    __float2half(accv[mt][nt][2*rr]   + bbv.x);
                g_vt[(((size_t)(bb * 256 + n + 1)) << 10) + hw] =
                    __float2half(accv[mt][nt][2*rr+1] + bbv.y);
            }
        }
    }
}

// ---------------------------------------------------------------------------
// Flash attention (fp16 mma, exp2, no running max), cp.async double-buffered.
// CTA = 128 queries (8 warps x m16); 16 key-tiles of 64.
// ---------------------------------------------------------------------------
__global__ void __launch_bounds__(256) attn_kernel()
{
    __shared__ __align__(16) __half Ks[2][64 * KVS];   // [key][dim]
    __shared__ __align__(16) __half Vt[2][64 * KVS];   // [dim][key]

    const int b  = blockIdx.z;
    const int h  = blockIdx.y;
    const int s0 = blockIdx.x * 128;
    const int tid = threadIdx.x;
    const int w = tid >> 5, lane = tid & 31, g = lane >> 2, t = lane & 3;

    const __half* kg = g_kh + (size_t)b * HWn * 256 + h * 64;          // stride 256
    const __half* vg = g_vt + (((size_t)(b * 256 + h * 64)) << 10);    // stride 1024

    const int cr0 = tid >> 3,         cc0 = (tid & 7) * 8;
    const int cr1 = (tid + 256) >> 3, cc1 = cc0;

    #pragma unroll
    for (int pc = 0; pc < 2; pc++) {
        const int jt = pc * 64;
        cpa16(&Ks[pc][cr0 * KVS + cc0], kg + (size_t)(jt + cr0) * 256 + cc0);
        cpa16(&Ks[pc][cr1 * KVS + cc1], kg + (size_t)(jt + cr1) * 256 + cc1);
        cpa16(&Vt[pc][cr0 * KVS + cc0], vg + (size_t)cr0 * 1024 + jt + cc0);
        cpa16(&Vt[pc][cr1 * KVS + cc1], vg + (size_t)cr1 * 1024 + jt + cc1);
        CP_COMMIT();
    }

    // Q fragments (already scaled by QSCALE in qproj)
    const __half* qbase = g_qh + ((size_t)(b * Sn + s0 + w * 16)) * 256 + h * 64;
    uint32_t Qfr[4][4];
    #pragma unroll
    for (int ks = 0; ks < 4; ks++) {
        const int d0 = ks * 16 + 2 * t;
        Qfr[ks][0] = *(const uint32_t*)(qbase + (size_t) g      * 256 + d0);
        Qfr[ks][1] = *(const uint32_t*)(qbase + (size_t)(g + 8) * 256 + d0);
        Qfr[ks][2] = *(const uint32_t*)(qbase + (size_t) g      * 256 + d0 + 8);
        Qfr[ks][3] = *(const uint32_t*)(qbase + (size_t)(g + 8) * 256 + d0 + 8);
    }

    float O[8][4];
    #pragma unroll
    for (int i = 0; i < 8; i++) { O[i][0] = O[i][1] = O[i][2] = O[i][3] = 0.f; }
    float l0 = 0.f, l1 = 0.f;
    const int r0 = s0 + w * 16 + g, r1 = r0 + 8;

    for (int it = 0; it < 16; it++) {
        const int jt = it * 64;
        CP_WAIT1();
        __syncthreads();
        const __half* Kb = Ks[it & 1];
        const __half* Vb = Vt[it & 1];

        // ---- S = Q K^T (log2-units) ----
        float S[8][4];
        #pragma unroll
        for (int nt = 0; nt < 8; nt++) { S[nt][0] = S[nt][1] = S[nt][2] = S[nt][3] = 0.f; }
        #pragma unroll
        for (int nt = 0; nt < 8; nt++) {
            const __half* kb = Kb + (nt * 8 + g) * KVS;
            #pragma unroll
            for (int ks = 0; ks < 4; ks++) {
                uint32_t b0 = *(const uint32_t*)(kb + ks * 16 + 2 * t);
                uint32_t b1 = *(const uint32_t*)(kb + ks * 16 + 2 * t + 8);
                mma_f16(S[nt], Qfr[ks], b0, b1);
            }
        }

        // ---- mask |col-row|<=WIN ----
        if (jt <= s0 + 130 && jt + 66 >= s0) {
            #pragma unroll
            for (int nt = 0; nt < 8; nt++) {
                const int c = jt + nt * 8 + 2 * t;
                if ((unsigned)(c     - r0 + WIN) <= 2u * WIN) S[nt][0] -= 1e9f;
                if ((unsigned)(c + 1 - r0 + WIN) <= 2u * WIN) S[nt][1] -= 1e9f;
                if ((unsigned)(c     - r1 + WIN) <= 2u * WIN) S[nt][2] -= 1e9f;
                if ((unsigned)(c + 1 - r1 + WIN) <= 2u * WIN) S[nt][3] -= 1e9f;
            }
        }

        // ---- P = exp2(S) as fp16 fragments; accumulate partial l ----
        uint32_t Pf[4][4];
        #pragma unroll
        for (int m = 0; m < 4; m++) {
            Pf[m][0] = h2exp2u(pack_h2(S[2*m  ][0], S[2*m  ][1]));
            Pf[m][1] = h2exp2u(pack_h2(S[2*m  ][2], S[2*m  ][3]));
            Pf[m][2] = h2exp2u(pack_h2(S[2*m+1][0], S[2*m+1][1]));
            Pf[m][3] = h2exp2u(pack_h2(S[2*m+1][2], S[2*m+1][3]));
            __half2 s0h = __hadd2(*reinterpret_cast<__half2*>(&Pf[m][0]),
                                  *reinterpret_cast<__half2*>(&Pf[m][2]));
            __half2 s1h = __hadd2(*reinterpret_cast<__half2*>(&Pf[m][1]),
                                  *reinterpret_cast<__half2*>(&Pf[m][3]));
            float2 f0 = __half22float2(s0h); l0 += f0.x + f0.y;
            float2 f1 = __half22float2(s1h); l1 += f1.x + f1.y;
        }

        // ---- O += P V ----
        #pragma unroll
        for (int m = 0; m < 4; m++) {
            #pragma unroll
            for (int dn = 0; dn < 8; dn++) {
                const __half* vb = Vb + (dn * 8 + g) * KVS + m * 16 + 2 * t;
                uint32_t b0 = *(const uint32_t*)(vb);
                uint32_t b1 = *(const uint32_t*)(vb + 8);
                mma_f16(O[dn], Pf[m], b0, b1);
            }
        }

        __syncthreads();
        if (it + 2 < 16) {
            const int nj = jt + 128, buf = it & 1;
            cpa16(&Ks[buf][cr0 * KVS + cc0], kg + (size_t)(nj + cr0) * 256 + cc0);
            cpa16(&Ks[buf][cr1 * KVS + cc1], kg + (size_t)(nj + cr1) * 256 + cc1);
            cpa16(&Vt[buf][cr0 * KVS + cc0], vg + (size_t)cr0 * 1024 + nj + cc0);
            cpa16(&Vt[buf][cr1 * KVS + cc1], vg + (size_t)cr1 * 1024 + nj + cc1);
        }
        CP_COMMIT();
    }

    // ---- epilogue: reduce l across t-group (BUGFIX), normalize, store ----
    l0 += __shfl_xor_sync(0xffffffffu, l0, 1);
    l0 += __shfl_xor_sync(0xffffffffu, l0, 2);
    l1 += __shfl_xor_sync(0xffffffffu, l1, 1);
    l1 += __shfl_xor_sync(0xffffffffu, l1, 2);
    const float inv0 = 1.f / l0, inv1 = 1.f / l1;
    __half* ob = g_aoh + ((size_t)(b * Sn + s0 + w * 16)) * 256 + h * 64;
    #pragma unroll
    for (int nt = 0; nt < 8; nt++) {
        const int n = nt * 8 + 2 * t;
        *reinterpret_cast<__half2*>(&ob[(size_t) g      * 256 + n]) =
            __floats2half2_rn(O[nt][0] * inv0, O[nt][1] * inv0);
        *reinterpret_cast<__half2*>(&ob[(size_t)(g + 8) * 256 + n]) =
            __floats2half2_rn(O[nt][2] * inv1, O[nt][3] * inv1);
    }
}

// ---------------------------------------------------------------------------
// Output projection + reshape-scatter + residual (fp16 GEMM, fp32 epilogue)
// ---------------------------------------------------------------------------
__global__ void __launch_bounds__(256) oproj_kernel(const float* __restrict__ x,
                                                    const float* __restrict__ bo,
                                                    float* __restrict__ out)
{
    __shared__ __align__(16) __half As[2][128 * ASTR];
    __shared__ __align__(16) __half Bs[2][64 * BSTR];
    const int tid = threadIdx.x;
    const int w = tid >> 5, lane = tid & 31, g = lane >> 2, t = lane & 3;
    const int wm = w >> 1, wn = w & 1;
    const int m0 = blockIdx.y * 128, n0 = blockIdx.x * 64;
    const __half* Ag = g_aoh + (size_t)m0 * 256;
    const __half* Bg = g_wot + (size_t)n0 * 256;

    const int ar0 = tid >> 2,         ac0 = (tid & 3) * 8;
    const int ar1 = (tid + 256) >> 2, ac1 = ac0;
    const int br  = tid >> 2,         bc  = (tid & 3) * 8;

    #pragma unroll
    for (int pc = 0; pc < 2; pc++) {
        cpa16(&As[pc][ar0 * ASTR + ac0], Ag + (size_t)ar0 * 256 + pc * 32 + ac0);
        cpa16(&As[pc][ar1 * ASTR + ac1], Ag + (size_t)ar1 * 256 + pc * 32 + ac1);
        cpa16(&Bs[pc][br * BSTR + bc],   Bg + (size_t)br * 256 + pc * 32 + bc);
        CP_COMMIT();
    }

    float acc[2][4][4] = {};
    for (int kc = 0; kc < 8; kc++) {
        CP_WAIT1();
        __syncthreads();
        const __half* Ab = As[kc & 1];
        const __half* Bb = Bs[kc & 1];
        #pragma unroll
        for (int ks = 0; ks < 2; ks++) {
            uint32_t a[2][4], bb[4][2];
            #pragma unroll
            for (int mt = 0; mt < 2; mt++) {
                const int r = wm * 32 + mt * 16 + g;
                a[mt][0] = *(const uint32_t*)(Ab + (r    ) * ASTR + ks * 16 + 2 * t);
                a[mt][1] = *(const uint32_t*)(Ab + (r + 8) * ASTR + ks * 16 + 2 * t);
                a[mt][2] = *(const uint32_t*)(Ab + (r    ) * ASTR + ks * 16 + 2 * t + 8);
                a[mt][3] = *(const uint32_t*)(Ab + (r + 8) * ASTR + ks * 16 + 2 * t + 8);
            }
            #pragma unroll
            for (int nt = 0; nt < 4; nt++) {
                const int r = wn * 32 + nt * 8 + g;
                bb[nt][0] = *(const uint32_t*)(Bb + r * BSTR + ks * 16 + 2 * t);
                bb[nt][1] = *(const uint32_t*)(Bb + r * BSTR + ks * 16 + 2 * t + 8);
            }
            #pragma unroll
            for (int mt = 0; mt < 2; mt++)
                #pragma unroll
                for (int nt = 0; nt < 4; nt++)
                    mma_f16(acc[mt][nt], a[mt], bb[nt][0], bb[nt][1]);
        }
        __syncthreads();
        if (kc + 2 < 8) {
            const int nk = kc + 2, buf = kc & 1;
            cpa16(&As[buf][ar0 * ASTR + ac0], Ag + (size_t)ar0 * 256 + nk * 32 + ac0);
            cpa16(&As[buf][ar1 * ASTR + ac1], Ag + (size_t)ar1 * 256 + nk * 32 + ac1);
            cpa16(&Bs[buf][br * BSTR + bc],   Bg + (size_t)br * 256 + nk * 32 + bc);
        }
        CP_COMMIT();
    }

    #pragma unroll
    for (int mt = 0; mt < 2; mt++) {
        const int row0 = m0 + wm * 32 + mt * 16 + g;
        #pragma unroll
        for (int nt = 0; nt < 4; nt++) {
            const int n = n0 + wn * 32 + nt * 8 + 2 * t;
            const float2 bb = *reinterpret_cast<const float2*>(&bo[n]);
            #pragma unroll
            for (int rr = 0; rr < 2; rr++) {
                const int m  = row0 + rr * 8;
                const int bv = m >> 10;
                const int hw = m & 1023;
                const size_t flat = ((size_t)(bv * 256 + (hw >> 2))) * 1024
                                  + (size_t)(hw & 3) * 256 + n;
                const float2 xr = *reinterpret_cast<const float2*>(&x[flat]);
                float2 o;
                o.x = acc[mt][nt][2*rr]   + bb.x + xr.x;
                o.y = acc[mt][nt][2*rr+1] + bb.y + xr.y;
                *reinterpret_cast<float2*>(&out[flat]) = o;
            }
        }
    }
}

// ---------------------------------------------------------------------------
extern "C" void kernel_launch(void* const* d_in, const int* in_sizes, int n_in,
                              void* d_out, int out_size)
{
    const float* x  = (const float*)d_in[0];
    const float* Wq = (const float*)d_in[1];
    const float* bq = (const float*)d_in[2];
    const float* Wk = (const float*)d_in[3];
    const float* bk = (const float*)d_in[4];
    const float* Wv = (const float*)d_in[5];
    const float* bv = (const float*)d_in[6];
    const float* Wo = (const float*)d_in[7];
    const float* bo = (const float*)d_in[8];
    float* out = (float*)d_out;

    prep_x <<<dim3(32, 8, 24), dim3(32, 8)>>>(x);
    prep_w <<<dim3(8, 48, 4),  dim3(32, 8)>>>(Wq, Wk, Wv, Wo);
    qproj_kernel <<<dim3(4, 192), 256>>>(bq);
    kvproj_kernel<<<dim3(4, 32),  256>>>(bk, bv);
    attn_kernel  <<<dim3(48, 4, 4), 256>>>();
    oproj_kernel <<<dim3(4, 192), 256>>>(x, bo, out);
}